// round 7
// baseline (speedup 1.0000x reference)
#include <cuda_runtime.h>
#include <cuda_bf16.h>
#include <cstdint>
#include <math.h>

#define SQ 2048
#define DQ 512
#define NB 8
#define MR (NB*SQ)   // 16384

// ============================================================================
// Scratch (device globals — allocation-free)
// ============================================================================
struct Scratch {
    __nv_bfloat16 xhi[3][(size_t)MR * DQ], xlo[3][(size_t)MR * DQ];   // split inputs
    __nv_bfloat16 qhi[(size_t)MR * DQ], qlo[(size_t)MR * DQ];
    __nv_bfloat16 khi[(size_t)MR * DQ], klo[(size_t)MR * DQ];
    __nv_bfloat16 vthi[(size_t)DQ * MR], vtlo[(size_t)DQ * MR];       // v transposed [d][s]
    __nv_bfloat16 wthi[3][DQ * DQ], wtlo[3][DQ * DQ];                 // W transposed [d][f]
    __nv_bfloat16 phi[(size_t)MR * SQ], plo[(size_t)MR * SQ];         // split normalized p
    float tmax[MR * 16], tsum[MR * 16];
};
__device__ Scratch g_s;

// ============================================================================
// PTX helpers (base-target features only: cp.async, ldmatrix, mma.sync)
// ============================================================================
__device__ __forceinline__ uint32_t smem_u32(const void* p) {
    uint32_t a;
    asm("{ .reg .u64 t; cvta.to.shared.u64 t, %1; cvt.u32.u64 %0, t; }" : "=r"(a) : "l"(p));
    return a;
}
__device__ __forceinline__ void cpa16(uint32_t dst, const void* src) {
    asm volatile("cp.async.cg.shared.global [%0], [%1], 16;" :: "r"(dst), "l"(src));
}
__device__ __forceinline__ void ldsm4(uint32_t* r, uint32_t addr) {
    asm volatile("ldmatrix.sync.aligned.m8n8.x4.shared.b16 {%0,%1,%2,%3}, [%4];"
        : "=r"(r[0]), "=r"(r[1]), "=r"(r[2]), "=r"(r[3]) : "r"(addr));
}
__device__ __forceinline__ void ldsm2(uint32_t* r, uint32_t addr) {
    asm volatile("ldmatrix.sync.aligned.m8n8.x2.shared.b16 {%0,%1}, [%2];"
        : "=r"(r[0]), "=r"(r[1]) : "r"(addr));
}
__device__ __forceinline__ void mma16816(float* c, const uint32_t* a, const uint32_t* b) {
    asm volatile(
        "mma.sync.aligned.m16n8k16.row.col.f32.bf16.bf16.f32 "
        "{%0,%1,%2,%3}, {%4,%5,%6,%7}, {%8,%9}, {%0,%1,%2,%3};"
        : "+f"(c[0]), "+f"(c[1]), "+f"(c[2]), "+f"(c[3])
        : "r"(a[0]), "r"(a[1]), "r"(a[2]), "r"(a[3]), "r"(b[0]), "r"(b[1]));
}
__device__ __forceinline__ void split2(float x, float y, uint32_t& hi, uint32_t& lo) {
    union { __nv_bfloat16 b[2]; uint32_t u; } H, L;
    H.b[0] = __float2bfloat16(x); H.b[1] = __float2bfloat16(y);
    L.b[0] = __float2bfloat16(x - __bfloat162float(H.b[0]));
    L.b[1] = __float2bfloat16(y - __bfloat162float(H.b[1]));
    hi = H.u; lo = L.u;
}

// ============================================================================
// SMEM: per stage (40960B): Ahi@0, Alo@10240, Bhi@20480, Blo@30720.
// Rows = 32 bf16 (64B) at 80B stride. 2 stages. Stats at 81920.
// ============================================================================
#define STG_STR  40960
#define OFF_ALO  10240
#define OFF_BHI  20480
#define OFF_BLO  30720
#define SM_STATS 81920
#define SM_TOTAL 86016
#define RSTRIDE  80

// ---- cp.async one K=32 chunk of all 4 tiles (2 threads/row, 2x16B each) ----
__device__ __forceinline__ void load_chunk(
    uint32_t sbu, int stg, int tid,
    const __nv_bfloat16* Ah, const __nv_bfloat16* Al,
    const __nv_bfloat16* Bh, const __nv_bfloat16* Bl,
    long long aBase, long long bBase, int lda, int ldb, int k0)
{
    const int lrow = tid >> 1;
    const int seg  = (tid & 1) * 16;
    const uint32_t sd = sbu + stg * STG_STR + lrow * RSTRIDE + seg * 2;
    const long long ga = aBase + (long long)lrow * lda + k0 + seg;
    const long long gb = bBase + (long long)lrow * ldb + k0 + seg;
    cpa16(sd,           Ah + ga); cpa16(sd + 16,           Ah + ga + 8);
    cpa16(sd + OFF_ALO, Al + ga); cpa16(sd + OFF_ALO + 16, Al + ga + 8);
    cpa16(sd + OFF_BHI, Bh + gb); cpa16(sd + OFF_BHI + 16, Bh + gb + 8);
    cpa16(sd + OFF_BLO, Bl + gb); cpa16(sd + OFF_BLO + 16, Bl + gb + 8);
    asm volatile("cp.async.commit_group;");
}

// ---- 3-pass split-bf16 mainloop, PASS-OUTER ordering (independent MMA streams)
__device__ __forceinline__ void gemm_mainloop(
    uint32_t sbu, int tid, int lane, int wm, int wn,
    const __nv_bfloat16* Ah, const __nv_bfloat16* Al,
    const __nv_bfloat16* Bh, const __nv_bfloat16* Bl,
    long long aBase, long long bBase, int lda, int ldb, int nchunks,
    float c[4][4][4])
{
    const int laneRowA = (lane & 7) + ((lane >> 3) & 1) * 8;
    const int laneColA = ((lane >> 4) & 1) * 16;
    const int laneRowB = lane & 7;
    const int laneColB = ((lane >> 3) & 1) * 16;

    // per-warp ldmatrix base addresses (offsets added in-loop)
    const uint32_t aAddr = (wm*64 + laneRowA) * RSTRIDE + laneColA;
    const uint32_t bAddr = (wn*32 + laneRowB) * RSTRIDE + laneColB;

    load_chunk(sbu, 0, tid, Ah, Al, Bh, Bl, aBase, bBase, lda, ldb, 0);
    load_chunk(sbu, 1, tid, Ah, Al, Bh, Bl, aBase, bBase, lda, ldb, 32);

    for (int ch = 0; ch < nchunks; ch++) {
        asm volatile("cp.async.wait_group 1;");
        __syncthreads();

        const uint32_t sb = sbu + (ch & 1) * STG_STR;
        #pragma unroll
        for (int h = 0; h < 2; h++) {
            const uint32_t hoff = h * 32;
            // --- B frags (once per half) ---
            uint32_t bh[4][2], bl[4][2];
            #pragma unroll
            for (int nt = 0; nt < 4; nt++) {
                const uint32_t rb = sb + bAddr + nt*8*RSTRIDE + hoff;
                ldsm2(bh[nt], rb + OFF_BHI);
                ldsm2(bl[nt], rb + OFF_BLO);
            }
            // --- pass 1: a_hi x b_hi ---
            uint32_t a[4][4];
            #pragma unroll
            for (int mt = 0; mt < 4; mt++)
                ldsm4(a[mt], sb + aAddr + mt*16*RSTRIDE + hoff);
            #pragma unroll
            for (int mt = 0; mt < 4; mt++)
                #pragma unroll
                for (int nt = 0; nt < 4; nt++)
                    mma16816(c[mt][nt], a[mt], bh[nt]);
            // --- pass 2: a_hi x b_lo (reuse a) ---
            #pragma unroll
            for (int mt = 0; mt < 4; mt++)
                #pragma unroll
                for (int nt = 0; nt < 4; nt++)
                    mma16816(c[mt][nt], a[mt], bl[nt]);
            // --- pass 3: a_lo x b_hi ---
            #pragma unroll
            for (int mt = 0; mt < 4; mt++)
                ldsm4(a[mt], sb + OFF_ALO + aAddr + mt*16*RSTRIDE + hoff);
            #pragma unroll
            for (int mt = 0; mt < 4; mt++)
                #pragma unroll
                for (int nt = 0; nt < 4; nt++)
                    mma16816(c[mt][nt], a[mt], bh[nt]);
        }
        __syncthreads();
        if (ch + 2 < nchunks)
            load_chunk(sbu, ch & 1, tid, Ah, Al, Bh, Bl, aBase, bBase, lda, ldb, (ch + 2) << 5);
        else
            asm volatile("cp.async.commit_group;");
    }
}

// ---- epilogue: store pre-split bf16 pair, row-major [row*DQ+col] ----
__device__ __forceinline__ void epi_pair(float c[4][4][4], int lane, int wm, int wn,
    long long bm, int bn, __nv_bfloat16* Oh, __nv_bfloat16* Ol)
{
    const int qrow = lane >> 2, qcol = (lane & 3) * 2;
    #pragma unroll
    for (int mt = 0; mt < 4; mt++)
        #pragma unroll
        for (int i = 0; i < 2; i++) {
            const long long row = bm + wm*64 + mt*16 + qrow + i*8;
            #pragma unroll
            for (int nt = 0; nt < 4; nt++) {
                const int col = bn + wn*32 + nt*8 + qcol;
                uint32_t hh, ll;
                split2(c[mt][nt][2*i], c[mt][nt][2*i+1], hh, ll);
                *(uint32_t*)(Oh + row*DQ + col) = hh;
                *(uint32_t*)(Ol + row*DQ + col) = ll;
            }
        }
}

// ---- epilogue: store pre-split bf16 pair transposed [col*MR + row] ----
__device__ __forceinline__ void epi_pairT(float c[4][4][4], int lane, int wm, int wn,
    long long bm, int bn, __nv_bfloat16* Oh, __nv_bfloat16* Ol)
{
    const int qrow = lane >> 2, qcol = (lane & 3) * 2;
    #pragma unroll
    for (int mt = 0; mt < 4; mt++)
        #pragma unroll
        for (int i = 0; i < 2; i++) {
            const long long row = bm + wm*64 + mt*16 + qrow + i*8;
            #pragma unroll
            for (int nt = 0; nt < 4; nt++)
                #pragma unroll
                for (int j = 0; j < 2; j++) {
                    const long long colg = bn + wn*32 + nt*8 + qcol + j;
                    const float f = c[mt][nt][2*i+j];
                    const __nv_bfloat16 hh = __float2bfloat16(f);
                    Oh[colg*MR + row] = hh;
                    Ol[colg*MR + row] = __float2bfloat16(f - __bfloat162float(hh));
                }
        }
}

// ============================================================================
// Fused projection kernel: z=0 -> q (pair), z=1 -> k (pair), z=2 -> v (pair^T)
// ============================================================================
__global__ __launch_bounds__(256)
void proj_gemm()
{
    extern __shared__ char smem[];
    const uint32_t sbu = smem_u32(smem);
    const int tid = threadIdx.x, lane = tid & 31, wid = tid >> 5;
    const int wm = wid >> 2, wn = wid & 3;
    const int bm = blockIdx.y << 7, bn = blockIdx.x << 7;
    const int z = blockIdx.z;

    float c[4][4][4];
    #pragma unroll
    for (int i = 0; i < 4; i++)
        #pragma unroll
        for (int j = 0; j < 4; j++)
            { c[i][j][0]=0.f; c[i][j][1]=0.f; c[i][j][2]=0.f; c[i][j][3]=0.f; }

    gemm_mainloop(sbu, tid, lane, wm, wn,
                  g_s.xhi[z], g_s.xlo[z], g_s.wthi[z], g_s.wtlo[z],
                  (long long)bm * DQ, (long long)bn * DQ, DQ, DQ, DQ >> 5, c);

    if (z == 0)      epi_pair (c, lane, wm, wn, bm, bn, g_s.qhi, g_s.qlo);
    else if (z == 1) epi_pair (c, lane, wm, wn, bm, bn, g_s.khi, g_s.klo);
    else             epi_pairT(c, lane, wm, wn, bm, bn, g_s.vthi, g_s.vtlo);
}

// ============================================================================
// QK kernel: raw logits (scale+mask, jax rounding) -> p, per-tile stats
// ============================================================================
__global__ __launch_bounds__(256)
void qk_gemm(float* __restrict__ outF, const float* __restrict__ mask)
{
    extern __shared__ char smem[];
    const uint32_t sbu = smem_u32(smem);
    const int tid = threadIdx.x, lane = tid & 31, wid = tid >> 5;
    const int wm = wid >> 2, wn = wid & 3;
    const int bm = blockIdx.y << 7, bn = blockIdx.x << 7;
    const long long zOff = (long long)blockIdx.z * SQ * DQ;

    float c[4][4][4];
    #pragma unroll
    for (int i = 0; i < 4; i++)
        #pragma unroll
        for (int j = 0; j < 4; j++)
            { c[i][j][0]=0.f; c[i][j][1]=0.f; c[i][j][2]=0.f; c[i][j][3]=0.f; }

    gemm_mainloop(sbu, tid, lane, wm, wn,
                  g_s.qhi, g_s.qlo, g_s.khi, g_s.klo,
                  zOff + (long long)bm * DQ, zOff + (long long)bn * DQ,
                  DQ, DQ, DQ >> 5, c);

    const float scale = 0.044194173824159216f;  // 1/sqrt(512)
    const int qrow = lane >> 2, qcol = (lane & 3) * 2;
    float* smax = (float*)(smem + SM_STATS);    // [4][128]
    float* ssum = smax + 512;
    #pragma unroll
    for (int mt = 0; mt < 4; mt++)
        #pragma unroll
        for (int i = 0; i < 2; i++) {
            const int rowLocal = wm*64 + mt*16 + qrow + i*8;
            const long long grow = (long long)blockIdx.z * SQ + bm + rowLocal;
            float s[8];
            #pragma unroll
            for (int nt = 0; nt < 4; nt++) {
                const int col = bn + wn*32 + nt*8 + qcol;
                const float2 m = *(const float2*)(mask + grow*SQ + col);
                s[2*nt]   = __fadd_rn(__fmul_rn(c[mt][nt][2*i],   scale), __fmul_rn(m.x, -1e9f));
                s[2*nt+1] = __fadd_rn(__fmul_rn(c[mt][nt][2*i+1], scale), __fmul_rn(m.y, -1e9f));
                *(float2*)(outF + grow*SQ + col) = make_float2(s[2*nt], s[2*nt+1]);
            }
            float mx = s[0];
            #pragma unroll
            for (int j = 1; j < 8; j++) mx = fmaxf(mx, s[j]);
            mx = fmaxf(mx, __shfl_xor_sync(0xffffffffu, mx, 1));
            mx = fmaxf(mx, __shfl_xor_sync(0xffffffffu, mx, 2));
            float es = 0.f;
            #pragma unroll
            for (int j = 0; j < 8; j++) es += __expf(s[j] - mx);
            es += __shfl_xor_sync(0xffffffffu, es, 1);
            es += __shfl_xor_sync(0xffffffffu, es, 2);
            if ((lane & 3) == 0) {
                smax[wn*128 + rowLocal] = mx;
                ssum[wn*128 + rowLocal] = es;
            }
        }
    __syncthreads();
    if (tid < 128) {
        float m = smax[tid];
        #pragma unroll
        for (int w = 1; w < 4; w++) m = fmaxf(m, smax[w*128 + tid]);
        float l = 0.f;
        #pragma unroll
        for (int w = 0; w < 4; w++)
            l += ssum[w*128 + tid] * __expf(smax[w*128 + tid] - m);
        const long long grow = (long long)blockIdx.z * SQ + bm + tid;
        g_s.tmax[grow*16 + blockIdx.x] = m;
        g_s.tsum[grow*16 + blockIdx.x] = l;
    }
}

// ============================================================================
// PV kernel: h = p @ v  (A = split normalized p, B = split v^T), fp32 out
// ============================================================================
__global__ __launch_bounds__(256)
void pv_gemm(float* __restrict__ outF)
{
    extern __shared__ char smem[];
    const uint32_t sbu = smem_u32(smem);
    const int tid = threadIdx.x, lane = tid & 31, wid = tid >> 5;
    const int wm = wid >> 2, wn = wid & 3;
    const int bm = blockIdx.y << 7, bn = blockIdx.x << 7;

    float c[4][4][4];
    #pragma unroll
    for (int i = 0; i < 4; i++)
        #pragma unroll
        for (int j = 0; j < 4; j++)
            { c[i][j][0]=0.f; c[i][j][1]=0.f; c[i][j][2]=0.f; c[i][j][3]=0.f; }

    gemm_mainloop(sbu, tid, lane, wm, wn,
                  g_s.phi, g_s.plo, g_s.vthi, g_s.vtlo,
                  ((long long)blockIdx.z * SQ + bm) * SQ,
                  (long long)bn * MR + (long long)blockIdx.z * SQ,
                  SQ, MR, SQ >> 5, c);

    const int qrow = lane >> 2, qcol = (lane & 3) * 2;
    #pragma unroll
    for (int mt = 0; mt < 4; mt++)
        #pragma unroll
        for (int i = 0; i < 2; i++) {
            const long long grow = (long long)blockIdx.z * SQ + bm + wm*64 + mt*16 + qrow + i*8;
            #pragma unroll
            for (int nt = 0; nt < 4; nt++) {
                const int col = bn + wn*32 + nt*8 + qcol;
                *(float2*)(outF + grow*DQ + col) =
                    make_float2(c[mt][nt][2*i], c[mt][nt][2*i+1]);
            }
        }
}

// ============================================================================
// Fused elementwise input split: z selects (qx, kx, vx) -> xhi[z], xlo[z]
// ============================================================================
__global__ __launch_bounds__(256)
void x_split(const float* __restrict__ X0, const float* __restrict__ X1,
             const float* __restrict__ X2)
{
    const int z = blockIdx.z;
    const float* X = (z == 0) ? X0 : (z == 1) ? X1 : X2;
    __nv_bfloat16* H = g_s.xhi[z];
    __nv_bfloat16* L = g_s.xlo[z];
    const size_t i = ((size_t)blockIdx.x * 256 + threadIdx.x) * 4;
    float4 v = *(const float4*)(X + i);
    uint32_t h0, l0, h1, l1;
    split2(v.x, v.y, h0, l0);
    split2(v.z, v.w, h1, l1);
    *(uint2*)(H + i) = make_uint2(h0, h1);
    *(uint2*)(L + i) = make_uint2(l0, l1);
}

// ============================================================================
// Fused weight transpose + split (smem-tiled): Wt[d][f] = split(W[f][d])
// grid (16,16,3), block (32,8)
// ============================================================================
__global__ __launch_bounds__(256)
void wt_split(const float* __restrict__ W0, const float* __restrict__ W1,
              const float* __restrict__ W2)
{
    const int z = blockIdx.z;
    const float* W = (z == 0) ? W0 : (z == 1) ? W1 : W2;
    __nv_bfloat16* Th = g_s.wthi[z];
    __nv_bfloat16* Tl = g_s.wtlo[z];
    __shared__ float t[32][33];
    const int bf = blockIdx.y << 5, bd = blockIdx.x << 5;
    const int tx = threadIdx.x, ty = threadIdx.y;
    #pragma unroll
    for (int r = 0; r < 4; r++)
        t[ty + r*8][tx] = W[(bf + ty + r*8) * DQ + bd + tx];
    __syncthreads();
    #pragma unroll
    for (int r = 0; r < 4; r++) {
        const float v = t[tx][ty + r*8];          // W[bf+tx][bd+ty+r*8]
        const int dd = bd + ty + r*8, f = bf + tx;
        const __nv_bfloat16 h = __float2bfloat16(v);
        Th[dd * DQ + f] = h;
        Tl[dd * DQ + f] = __float2bfloat16(v - __bfloat162float(h));
    }
}

// ============================================================================
// Softmax normalize + split: p = exp(s-m)/l (fp32 out) and (hi, lo) bf16
// ============================================================================
__global__ __launch_bounds__(256)
void softmax_norm_kernel(float* __restrict__ p)
{
    const int g = blockIdx.x;
    __shared__ float sh[2];
    if (threadIdx.x == 0) {
        float m = __int_as_float(0xff800000);
        #pragma unroll
        for (int t = 0; t < 16; t++) m = fmaxf(m, g_s.tmax[g * 16 + t]);
        float l = 0.f;
        #pragma unroll
        for (int t = 0; t < 16; t++)
            l += g_s.tsum[g * 16 + t] * __expf(g_s.tmax[g * 16 + t] - m);
        sh[0] = m;
        sh[1] = 1.f / l;
    }
    __syncthreads();
    const float m = sh[0], inv = sh[1];
    float* row = p + (size_t)g * SQ;
    __nv_bfloat16* ph = g_s.phi + (size_t)g * SQ;
    __nv_bfloat16* pl = g_s.plo + (size_t)g * SQ;
    #pragma unroll
    for (int it = 0; it < 2; it++) {
        const int i = (threadIdx.x << 2) + (it << 10);
        float4 v = *(float4*)&row[i];
        v.x = __expf(v.x - m) * inv;
        v.y = __expf(v.y - m) * inv;
        v.z = __expf(v.z - m) * inv;
        v.w = __expf(v.w - m) * inv;
        *(float4*)&row[i] = v;
        uint32_t h0, l0, h1, l1;
        split2(v.x, v.y, h0, l0);
        split2(v.z, v.w, h1, l1);
        *(uint2*)(ph + i) = make_uint2(h0, h1);
        *(uint2*)(pl + i) = make_uint2(l0, l1);
    }
}

// ============================================================================
// Host launcher (graph-capturable: kernel launches only)
// ============================================================================
extern "C" void kernel_launch(void* const* d_in, const int* in_sizes, int n_in,
                              void* d_out, int out_size)
{
    const float* qx   = (const float*)d_in[0];
    const float* kx   = (const float*)d_in[1];
    const float* vx   = (const float*)d_in[2];
    const float* mask = (const float*)d_in[3];
    const float* Wq   = (const float*)d_in[4];
    const float* Wk   = (const float*)d_in[5];
    const float* Wv   = (const float*)d_in[6];

    float* h = (float*)d_out;                  // [8,2048,512]
    float* p = h + (size_t)MR * DQ;            // [8,2048,2048]

    static bool attr_done = false;
    if (!attr_done) {
        cudaFuncSetAttribute(proj_gemm, cudaFuncAttributeMaxDynamicSharedMemorySize, SM_TOTAL);
        cudaFuncSetAttribute(qk_gemm,   cudaFuncAttributeMaxDynamicSharedMemorySize, SM_TOTAL);
        cudaFuncSetAttribute(pv_gemm,   cudaFuncAttributeMaxDynamicSharedMemorySize, SM_TOTAL);
        attr_done = true;
    }

    // 1) split inputs + transpose/split weights (fused over z=3)
    x_split<<<dim3((MR * DQ) / 1024, 1, 3), 256>>>(qx, kx, vx);
    wt_split<<<dim3(16, 16, 3), dim3(32, 8)>>>(Wq, Wk, Wv);

    // 2) fused projections (z: 0=q, 1=k, 2=v-transposed)
    proj_gemm<<<dim3(4, 128, 3), 256, SM_TOTAL>>>();

    // 3) QK^T + scale + mask -> raw logits in p + per-tile stats
    qk_gemm<<<dim3(16, 16, NB), 256, SM_TOTAL>>>(p, mask);

    // 4) normalize p in place + emit split bf16 p
    softmax_norm_kernel<<<dim3(MR), 256>>>(p);

    // 5) h = p @ v
    pv_gemm<<<dim3(4, 16, NB), 256, SM_TOTAL>>>(h);
}

// round 8
// speedup vs baseline: 1.3346x; 1.3346x over previous
#include <cuda_runtime.h>
#include <cuda_fp16.h>
#include <cstdint>
#include <math.h>

#define SQ 2048
#define DQ 512
#define NB 8
#define MR (NB*SQ)   // 16384

// ============================================================================
// Scratch (device globals — allocation-free)
// ============================================================================
struct Scratch {
    __half xhi[3][(size_t)MR * DQ], xlo[3][(size_t)MR * DQ];  // split inputs (A side)
    __half qhi[(size_t)MR * DQ], qlo[(size_t)MR * DQ];        // split q (A of QK)
    __half khi[(size_t)MR * DQ];                              // k hi only (B of QK)
    __half vthi[(size_t)DQ * MR];                             // v^T hi only (B of PV)
    __half wthi[3][DQ * DQ];                                  // W^T hi only (B of proj)
    __half phi[(size_t)MR * SQ], plo[(size_t)MR * SQ];        // split normalized p (A of PV)
    float tmax[MR * 16], tsum[MR * 16];
};
__device__ Scratch g_s;

// ============================================================================
// PTX helpers (base-target features only: cp.async, ldmatrix, mma.sync)
// ============================================================================
__device__ __forceinline__ uint32_t smem_u32(const void* p) {
    uint32_t a;
    asm("{ .reg .u64 t; cvta.to.shared.u64 t, %1; cvt.u32.u64 %0, t; }" : "=r"(a) : "l"(p));
    return a;
}
__device__ __forceinline__ void cpa16(uint32_t dst, const void* src) {
    asm volatile("cp.async.cg.shared.global [%0], [%1], 16;" :: "r"(dst), "l"(src));
}
__device__ __forceinline__ void ldsm4(uint32_t* r, uint32_t addr) {
    asm volatile("ldmatrix.sync.aligned.m8n8.x4.shared.b16 {%0,%1,%2,%3}, [%4];"
        : "=r"(r[0]), "=r"(r[1]), "=r"(r[2]), "=r"(r[3]) : "r"(addr));
}
__device__ __forceinline__ void ldsm2(uint32_t* r, uint32_t addr) {
    asm volatile("ldmatrix.sync.aligned.m8n8.x2.shared.b16 {%0,%1}, [%2];"
        : "=r"(r[0]), "=r"(r[1]) : "r"(addr));
}
__device__ __forceinline__ void mma16816(float* c, const uint32_t* a, const uint32_t* b) {
    asm volatile(
        "mma.sync.aligned.m16n8k16.row.col.f32.f16.f16.f32 "
        "{%0,%1,%2,%3}, {%4,%5,%6,%7}, {%8,%9}, {%0,%1,%2,%3};"
        : "+f"(c[0]), "+f"(c[1]), "+f"(c[2]), "+f"(c[3])
        : "r"(a[0]), "r"(a[1]), "r"(a[2]), "r"(a[3]), "r"(b[0]), "r"(b[1]));
}
// fp16 hi/lo split of two floats, packed
__device__ __forceinline__ void split2h(float x, float y, uint32_t& hi, uint32_t& lo) {
    union { __half b[2]; uint32_t u; } H, L;
    H.b[0] = __float2half_rn(x); H.b[1] = __float2half_rn(y);
    L.b[0] = __float2half_rn(x - __half2float(H.b[0]));
    L.b[1] = __float2half_rn(y - __half2float(H.b[1]));
    hi = H.u; lo = L.u;
}

// ============================================================================
// SMEM: per stage (30720B): Ahi@0, Alo@10240, Bhi@20480.
// Rows = 32 fp16 (64B) at 80B stride. 3 stages. Stats at 92160.
// Total 96256B -> 2 CTAs/SM.
// ============================================================================
#define STG_STR  30720
#define OFF_ALO  10240
#define OFF_BHI  20480
#define SM_STATS 92160
#define SM_TOTAL 96256
#define RSTRIDE  80

// ---- cp.async one K=32 chunk of 3 tiles (2 threads/row, 2x16B each) ----
__device__ __forceinline__ void load_chunk(
    uint32_t sbu, int stg, int tid,
    const __half* Ah, const __half* Al, const __half* Bh,
    long long aBase, long long bBase, int lda, int ldb, int k0)
{
    const int lrow = tid >> 1;
    const int seg  = (tid & 1) * 16;
    const uint32_t sd = sbu + stg * STG_STR + lrow * RSTRIDE + seg * 2;
    const long long ga = aBase + (long long)lrow * lda + k0 + seg;
    const long long gb = bBase + (long long)lrow * ldb + k0 + seg;
    cpa16(sd,           Ah + ga); cpa16(sd + 16,           Ah + ga + 8);
    cpa16(sd + OFF_ALO, Al + ga); cpa16(sd + OFF_ALO + 16, Al + ga + 8);
    cpa16(sd + OFF_BHI, Bh + gb); cpa16(sd + OFF_BHI + 16, Bh + gb + 8);
    asm volatile("cp.async.commit_group;");
}

// ---- 2-pass split-fp16 mainloop: C(128x128) += (A_hi + A_lo)[128,K] * B_hi[128,K]^T
// 3-stage cp.async pipeline, ONE __syncthreads per chunk.
__device__ __forceinline__ void gemm_mainloop(
    uint32_t sbu, int tid, int lane, int wm, int wn,
    const __half* Ah, const __half* Al, const __half* Bh,
    long long aBase, long long bBase, int lda, int ldb, int nchunks,
    float c[4][4][4])
{
    const int laneRowA = (lane & 7) + ((lane >> 3) & 1) * 8;
    const int laneColA = ((lane >> 4) & 1) * 16;
    const int laneRowB = lane & 7;
    const int laneColB = ((lane >> 3) & 1) * 16;

    const uint32_t aAddr = (wm*64 + laneRowA) * RSTRIDE + laneColA;
    const uint32_t bAddr = (wn*32 + laneRowB) * RSTRIDE + laneColB;

    load_chunk(sbu, 0, tid, Ah, Al, Bh, aBase, bBase, lda, ldb, 0);
    load_chunk(sbu, 1, tid, Ah, Al, Bh, aBase, bBase, lda, ldb, 32);

    int stg = 2;
    for (int ch = 0; ch < nchunks; ch++) {
        asm volatile("cp.async.wait_group 1;");
        __syncthreads();

        // issue next load immediately (buffer (ch+2)%3 was drained at iter ch-1,
        // guaranteed by the barrier above)
        if (ch + 2 < nchunks)
            load_chunk(sbu, stg, tid, Ah, Al, Bh, aBase, bBase, lda, ldb, (ch + 2) << 5);
        else
            asm volatile("cp.async.commit_group;");
        stg = (stg == 2) ? 0 : stg + 1;

        const uint32_t sb = sbu + (ch % 3) * STG_STR;
        #pragma unroll
        for (int h = 0; h < 2; h++) {
            const uint32_t hoff = h * 32;
            uint32_t bh[4][2];
            #pragma unroll
            for (int nt = 0; nt < 4; nt++)
                ldsm2(bh[nt], sb + OFF_BHI + bAddr + nt*8*RSTRIDE + hoff);
            uint32_t a[4][4];
            // pass 1: A_hi x B_hi
            #pragma unroll
            for (int mt = 0; mt < 4; mt++)
                ldsm4(a[mt], sb + aAddr + mt*16*RSTRIDE + hoff);
            #pragma unroll
            for (int mt = 0; mt < 4; mt++)
                #pragma unroll
                for (int nt = 0; nt < 4; nt++)
                    mma16816(c[mt][nt], a[mt], bh[nt]);
            // pass 2: A_lo x B_hi
            #pragma unroll
            for (int mt = 0; mt < 4; mt++)
                ldsm4(a[mt], sb + OFF_ALO + aAddr + mt*16*RSTRIDE + hoff);
            #pragma unroll
            for (int mt = 0; mt < 4; mt++)
                #pragma unroll
                for (int nt = 0; nt < 4; nt++)
                    mma16816(c[mt][nt], a[mt], bh[nt]);
        }
    }
}

// ---- epilogue: store fp16 hi/lo pair, row-major [row*DQ+col] (q) ----
__device__ __forceinline__ void epi_pair(float c[4][4][4], int lane, int wm, int wn,
    long long bm, int bn, __half* Oh, __half* Ol)
{
    const int qrow = lane >> 2, qcol = (lane & 3) * 2;
    #pragma unroll
    for (int mt = 0; mt < 4; mt++)
        #pragma unroll
        for (int i = 0; i < 2; i++) {
            const long long row = bm + wm*64 + mt*16 + qrow + i*8;
            #pragma unroll
            for (int nt = 0; nt < 4; nt++) {
                const int col = bn + wn*32 + nt*8 + qcol;
                uint32_t hh, ll;
                split2h(c[mt][nt][2*i], c[mt][nt][2*i+1], hh, ll);
                *(uint32_t*)(Oh + row*DQ + col) = hh;
                *(uint32_t*)(Ol + row*DQ + col) = ll;
            }
        }
}

// ---- epilogue: store fp16 hi only, row-major (k) ----
__device__ __forceinline__ void epi_hi(float c[4][4][4], int lane, int wm, int wn,
    long long bm, int bn, __half* Oh)
{
    const int qrow = lane >> 2, qcol = (lane & 3) * 2;
    #pragma unroll
    for (int mt = 0; mt < 4; mt++)
        #pragma unroll
        for (int i = 0; i < 2; i++) {
            const long long row = bm + wm*64 + mt*16 + qrow + i*8;
            #pragma unroll
            for (int nt = 0; nt < 4; nt++) {
                const int col = bn + wn*32 + nt*8 + qcol;
                union { __half b[2]; uint32_t u; } H;
                H.b[0] = __float2half_rn(c[mt][nt][2*i]);
                H.b[1] = __float2half_rn(c[mt][nt][2*i+1]);
                *(uint32_t*)(Oh + row*DQ + col) = H.u;
            }
        }
}

// ---- epilogue: store fp16 hi only, transposed [col*MR + row] (v^T) ----
__device__ __forceinline__ void epi_hiT(float c[4][4][4], int lane, int wm, int wn,
    long long bm, int bn, __half* Oh)
{
    const int qrow = lane >> 2, qcol = (lane & 3) * 2;
    #pragma unroll
    for (int mt = 0; mt < 4; mt++)
        #pragma unroll
        for (int i = 0; i < 2; i++) {
            const long long row = bm + wm*64 + mt*16 + qrow + i*8;
            #pragma unroll
            for (int nt = 0; nt < 4; nt++)
                #pragma unroll
                for (int j = 0; j < 2; j++) {
                    const long long colg = bn + wn*32 + nt*8 + qcol + j;
                    Oh[colg*MR + row] = __float2half_rn(c[mt][nt][2*i+j]);
                }
        }
}

// ============================================================================
// Fused projection kernel: z=0 -> q (pair), z=1 -> k (hi), z=2 -> v (hi^T)
// ============================================================================
__global__ __launch_bounds__(256)
void proj_gemm()
{
    extern __shared__ char smem[];
    const uint32_t sbu = smem_u32(smem);
    const int tid = threadIdx.x, lane = tid & 31, wid = tid >> 5;
    const int wm = wid >> 2, wn = wid & 3;
    const int bm = blockIdx.y << 7, bn = blockIdx.x << 7;
    const int z = blockIdx.z;

    float c[4][4][4];
    #pragma unroll
    for (int i = 0; i < 4; i++)
        #pragma unroll
        for (int j = 0; j < 4; j++)
            { c[i][j][0]=0.f; c[i][j][1]=0.f; c[i][j][2]=0.f; c[i][j][3]=0.f; }

    gemm_mainloop(sbu, tid, lane, wm, wn,
                  g_s.xhi[z], g_s.xlo[z], g_s.wthi[z],
                  (long long)bm * DQ, (long long)bn * DQ, DQ, DQ, DQ >> 5, c);

    if (z == 0)      epi_pair(c, lane, wm, wn, bm, bn, g_s.qhi, g_s.qlo);
    else if (z == 1) epi_hi  (c, lane, wm, wn, bm, bn, g_s.khi);
    else             epi_hiT (c, lane, wm, wn, bm, bn, g_s.vthi);
}

// ============================================================================
// QK kernel: raw logits (scale+mask, jax rounding) -> p, per-tile stats
// ============================================================================
__global__ __launch_bounds__(256)
void qk_gemm(float* __restrict__ outF, const float* __restrict__ mask)
{
    extern __shared__ char smem[];
    const uint32_t sbu = smem_u32(smem);
    const int tid = threadIdx.x, lane = tid & 31, wid = tid >> 5;
    const int wm = wid >> 2, wn = wid & 3;
    const int bm = blockIdx.y << 7, bn = blockIdx.x << 7;
    const long long zOff = (long long)blockIdx.z * SQ * DQ;

    float c[4][4][4];
    #pragma unroll
    for (int i = 0; i < 4; i++)
        #pragma unroll
        for (int j = 0; j < 4; j++)
            { c[i][j][0]=0.f; c[i][j][1]=0.f; c[i][j][2]=0.f; c[i][j][3]=0.f; }

    gemm_mainloop(sbu, tid, lane, wm, wn,
                  g_s.qhi, g_s.qlo, g_s.khi,
                  zOff + (long long)bm * DQ, zOff + (long long)bn * DQ,
                  DQ, DQ, DQ >> 5, c);

    const float scale = 0.044194173824159216f;  // 1/sqrt(512)
    const int qrow = lane >> 2, qcol = (lane & 3) * 2;
    float* smax = (float*)(smem + SM_STATS);    // [4][128]
    float* ssum = smax + 512;
    #pragma unroll
    for (int mt = 0; mt < 4; mt++)
        #pragma unroll
        for (int i = 0; i < 2; i++) {
            const int rowLocal = wm*64 + mt*16 + qrow + i*8;
            const long long grow = (long long)blockIdx.z * SQ + bm + rowLocal;
            float s[8];
            #pragma unroll
            for (int nt = 0; nt < 4; nt++) {
                const int col = bn + wn*32 + nt*8 + qcol;
                const float2 m = *(const float2*)(mask + grow*SQ + col);
                s[2*nt]   = __fadd_rn(__fmul_rn(c[mt][nt][2*i],   scale), __fmul_rn(m.x, -1e9f));
                s[2*nt+1] = __fadd_rn(__fmul_rn(c[mt][nt][2*i+1], scale), __fmul_rn(m.y, -1e9f));
                *(float2*)(outF + grow*SQ + col) = make_float2(s[2*nt], s[2*nt+1]);
            }
            float mx = s[0];
            #pragma unroll
            for (int j = 1; j < 8; j++) mx = fmaxf(mx, s[j]);
            mx = fmaxf(mx, __shfl_xor_sync(0xffffffffu, mx, 1));
            mx = fmaxf(mx, __shfl_xor_sync(0xffffffffu, mx, 2));
            float es = 0.f;
            #pragma unroll
            for (int j = 0; j < 8; j++) es += __expf(s[j] - mx);
            es += __shfl_xor_sync(0xffffffffu, es, 1);
            es += __shfl_xor_sync(0xffffffffu, es, 2);
            if ((lane & 3) == 0) {
                smax[wn*128 + rowLocal] = mx;
                ssum[wn*128 + rowLocal] = es;
            }
        }
    __syncthreads();
    if (tid < 128) {
        float m = smax[tid];
        #pragma unroll
        for (int w = 1; w < 4; w++) m = fmaxf(m, smax[w*128 + tid]);
        float l = 0.f;
        #pragma unroll
        for (int w = 0; w < 4; w++)
            l += ssum[w*128 + tid] * __expf(smax[w*128 + tid] - m);
        const long long grow = (long long)blockIdx.z * SQ + bm + tid;
        g_s.tmax[grow*16 + blockIdx.x] = m;
        g_s.tsum[grow*16 + blockIdx.x] = l;
    }
}

// ============================================================================
// PV kernel: h = p @ v  (A = split p, B = v^T hi), fp32 out
// ============================================================================
__global__ __launch_bounds__(256)
void pv_gemm(float* __restrict__ outF)
{
    extern __shared__ char smem[];
    const uint32_t sbu = smem_u32(smem);
    const int tid = threadIdx.x, lane = tid & 31, wid = tid >> 5;
    const int wm = wid >> 2, wn = wid & 3;
    const int bm = blockIdx.y << 7, bn = blockIdx.x << 7;

    float c[4][4][4];
    #pragma unroll
    for (int i = 0; i < 4; i++)
        #pragma unroll
        for (int j = 0; j < 4; j++)
            { c[i][j][0]=0.f; c[i][j][1]=0.f; c[i][j][2]=0.f; c[i][j][3]=0.f; }

    gemm_mainloop(sbu, tid, lane, wm, wn,
                  g_s.phi, g_s.plo, g_s.vthi,
                  ((long long)blockIdx.z * SQ + bm) * SQ,
                  (long long)bn * MR + (long long)blockIdx.z * SQ,
                  SQ, MR, SQ >> 5, c);

    const int qrow = lane >> 2, qcol = (lane & 3) * 2;
    #pragma unroll
    for (int mt = 0; mt < 4; mt++)
        #pragma unroll
        for (int i = 0; i < 2; i++) {
            const long long grow = (long long)blockIdx.z * SQ + bm + wm*64 + mt*16 + qrow + i*8;
            #pragma unroll
            for (int nt = 0; nt < 4; nt++) {
                const int col = bn + wn*32 + nt*8 + qcol;
                *(float2*)(outF + grow*DQ + col) =
                    make_float2(c[mt][nt][2*i], c[mt][nt][2*i+1]);
            }
        }
}

// ============================================================================
// Fused elementwise input split: z selects (qx, kx, vx) -> xhi[z], xlo[z]
// ============================================================================
__global__ __launch_bounds__(256)
void x_split(const float* __restrict__ X0, const float* __restrict__ X1,
             const float* __restrict__ X2)
{
    const int z = blockIdx.z;
    const float* X = (z == 0) ? X0 : (z == 1) ? X1 : X2;
    __half* H = g_s.xhi[z];
    __half* L = g_s.xlo[z];
    const size_t i = ((size_t)blockIdx.x * 256 + threadIdx.x) * 4;
    float4 v = *(const float4*)(X + i);
    uint32_t h0, l0, h1, l1;
    split2h(v.x, v.y, h0, l0);
    split2h(v.z, v.w, h1, l1);
    *(uint2*)(H + i) = make_uint2(h0, h1);
    *(uint2*)(L + i) = make_uint2(l0, l1);
}

// ============================================================================
// Fused weight transpose (smem-tiled), hi only: Wt[d][f] = fp16(W[f][d])
// grid (16,16,3), block (32,8)
// ============================================================================
__global__ __launch_bounds__(256)
void wt_split(const float* __restrict__ W0, const float* __restrict__ W1,
              const float* __restrict__ W2)
{
    const int z = blockIdx.z;
    const float* W = (z == 0) ? W0 : (z == 1) ? W1 : W2;
    __half* Th = g_s.wthi[z];
    __shared__ float t[32][33];
    const int bf = blockIdx.y << 5, bd = blockIdx.x << 5;
    const int tx = threadIdx.x, ty = threadIdx.y;
    #pragma unroll
    for (int r = 0; r < 4; r++)
        t[ty + r*8][tx] = W[(bf + ty + r*8) * DQ + bd + tx];
    __syncthreads();
    #pragma unroll
    for (int r = 0; r < 4; r++) {
        const float v = t[tx][ty + r*8];
        const int dd = bd + ty + r*8, f = bf + tx;
        Th[dd * DQ + f] = __float2half_rn(v);
    }
}

// ============================================================================
// Softmax normalize + split: p = exp(s-m)/l (fp32 out) and (hi, lo) fp16
// ============================================================================
__global__ __launch_bounds__(256)
void softmax_norm_kernel(float* __restrict__ p)
{
    const int g = blockIdx.x;
    __shared__ float sh[2];
    if (threadIdx.x == 0) {
        float m = __int_as_float(0xff800000);
        #pragma unroll
        for (int t = 0; t < 16; t++) m = fmaxf(m, g_s.tmax[g * 16 + t]);
        float l = 0.f;
        #pragma unroll
        for (int t = 0; t < 16; t++)
            l += g_s.tsum[g * 16 + t] * __expf(g_s.tmax[g * 16 + t] - m);
        sh[0] = m;
        sh[1] = 1.f / l;
    }
    __syncthreads();
    const float m = sh[0], inv = sh[1];
    float* row = p + (size_t)g * SQ;
    __half* ph = g_s.phi + (size_t)g * SQ;
    __half* pl = g_s.plo + (size_t)g * SQ;
    #pragma unroll
    for (int it = 0; it < 2; it++) {
        const int i = (threadIdx.x << 2) + (it << 10);
        float4 v = *(float4*)&row[i];
        v.x = __expf(v.x - m) * inv;
        v.y = __expf(v.y - m) * inv;
        v.z = __expf(v.z - m) * inv;
        v.w = __expf(v.w - m) * inv;
        *(float4*)&row[i] = v;
        uint32_t h0, l0, h1, l1;
        split2h(v.x, v.y, h0, l0);
        split2h(v.z, v.w, h1, l1);
        *(uint2*)(ph + i) = make_uint2(h0, h1);
        *(uint2*)(pl + i) = make_uint2(l0, l1);
    }
}

// ============================================================================
// Host launcher (graph-capturable: kernel launches only)
// ============================================================================
extern "C" void kernel_launch(void* const* d_in, const int* in_sizes, int n_in,
                              void* d_out, int out_size)
{
    const float* qx   = (const float*)d_in[0];
    const float* kx   = (const float*)d_in[1];
    const float* vx   = (const float*)d_in[2];
    const float* mask = (const float*)d_in[3];
    const float* Wq   = (const float*)d_in[4];
    const float* Wk   = (const float*)d_in[5];
    const float* Wv   = (const float*)d_in[6];

    float* h = (float*)d_out;                  // [8,2048,512]
    float* p = h + (size_t)MR * DQ;            // [8,2048,2048]

    static bool attr_done = false;
    if (!attr_done) {
        cudaFuncSetAttribute(proj_gemm, cudaFuncAttributeMaxDynamicSharedMemorySize, SM_TOTAL);
        cudaFuncSetAttribute(qk_gemm,   cudaFuncAttributeMaxDynamicSharedMemorySize, SM_TOTAL);
        cudaFuncSetAttribute(pv_gemm,   cudaFuncAttributeMaxDynamicSharedMemorySize, SM_TOTAL);
        attr_done = true;
    }

    // 1) split inputs + transpose weights (fused over z=3)
    x_split<<<dim3((MR * DQ) / 1024, 1, 3), 256>>>(qx, kx, vx);
    wt_split<<<dim3(16, 16, 3), dim3(32, 8)>>>(Wq, Wk, Wv);

    // 2) fused projections (z: 0=q pair, 1=k hi, 2=v hi^T)
    proj_gemm<<<dim3(4, 128, 3), 256, SM_TOTAL>>>();

    // 3) QK^T + scale + mask -> raw logits in p + per-tile stats
    qk_gemm<<<dim3(16, 16, NB), 256, SM_TOTAL>>>(p, mask);

    // 4) normalize p in place + emit split fp16 p
    softmax_norm_kernel<<<dim3(MR), 256>>>(p);

    // 5) h = p @ v
    pv_gemm<<<dim3(4, 16, NB), 256, SM_TOTAL>>>(h);
}

// round 9
// speedup vs baseline: 1.7966x; 1.3462x over previous
#include <cuda_runtime.h>
#include <cuda_fp16.h>
#include <cstdint>
#include <math.h>

#define SQ 2048
#define DQ 512
#define NB 8
#define MR (NB*SQ)   // 16384

// ============================================================================
// Scratch (device globals — allocation-free)
// ============================================================================
struct Scratch {
    __half xhi[3][(size_t)MR * DQ], xlo[3][(size_t)MR * DQ];  // split inputs (A of proj)
    __half qhi[(size_t)MR * DQ];                              // q hi (A of QK, 1-pass)
    __half khi[(size_t)MR * DQ];                              // k hi (B of QK)
    __half vthi[(size_t)DQ * MR];                             // v^T hi (B of PV)
    __half wthi[3][DQ * DQ];                                  // W^T hi (B of proj)
    __half phi[(size_t)MR * SQ];                              // normalized p hi (A of PV)
    float tmax[MR * 16], tsum[MR * 16];
};
__device__ Scratch g_s;

// ============================================================================
// PTX helpers (base-target features only: cp.async, ldmatrix, mma.sync)
// ============================================================================
__device__ __forceinline__ uint32_t smem_u32(const void* p) {
    uint32_t a;
    asm("{ .reg .u64 t; cvta.to.shared.u64 t, %1; cvt.u32.u64 %0, t; }" : "=r"(a) : "l"(p));
    return a;
}
__device__ __forceinline__ void cpa16(uint32_t dst, const void* src) {
    asm volatile("cp.async.cg.shared.global [%0], [%1], 16;" :: "r"(dst), "l"(src));
}
__device__ __forceinline__ void ldsm4(uint32_t* r, uint32_t addr) {
    asm volatile("ldmatrix.sync.aligned.m8n8.x4.shared.b16 {%0,%1,%2,%3}, [%4];"
        : "=r"(r[0]), "=r"(r[1]), "=r"(r[2]), "=r"(r[3]) : "r"(addr));
}
__device__ __forceinline__ void ldsm2(uint32_t* r, uint32_t addr) {
    asm volatile("ldmatrix.sync.aligned.m8n8.x2.shared.b16 {%0,%1}, [%2];"
        : "=r"(r[0]), "=r"(r[1]) : "r"(addr));
}
__device__ __forceinline__ void mma16816(float* c, const uint32_t* a, const uint32_t* b) {
    asm volatile(
        "mma.sync.aligned.m16n8k16.row.col.f32.f16.f16.f32 "
        "{%0,%1,%2,%3}, {%4,%5,%6,%7}, {%8,%9}, {%0,%1,%2,%3};"
        : "+f"(c[0]), "+f"(c[1]), "+f"(c[2]), "+f"(c[3])
        : "r"(a[0]), "r"(a[1]), "r"(a[2]), "r"(a[3]), "r"(b[0]), "r"(b[1]));
}
// fp16 hi/lo split of two floats, packed
__device__ __forceinline__ void split2h(float x, float y, uint32_t& hi, uint32_t& lo) {
    union { __half b[2]; uint32_t u; } H, L;
    H.b[0] = __float2half_rn(x); H.b[1] = __float2half_rn(y);
    L.b[0] = __float2half_rn(x - __half2float(H.b[0]));
    L.b[1] = __float2half_rn(y - __half2float(H.b[1]));
    hi = H.u; lo = L.u;
}
__device__ __forceinline__ uint32_t pack2h(float x, float y) {
    union { __half b[2]; uint32_t u; } H;
    H.b[0] = __float2half_rn(x); H.b[1] = __float2half_rn(y);
    return H.u;
}

// ============================================================================
// SMEM: per stage (30720B): Ahi@0, Alo@10240, Bhi@20480.
// Rows = 32 fp16 (64B) at 80B stride. 3 stages. Stats at 92160.
// Total 96256B -> 2 CTAs/SM.
// ============================================================================
#define STG_STR  30720
#define OFF_ALO  10240
#define OFF_BHI  20480
#define SM_STATS 92160
#define SM_TOTAL 96256
#define RSTRIDE  80

// ---- cp.async one K=32 chunk (2 threads/row, 2x16B per tile-row) ----
template<int NPASS>
__device__ __forceinline__ void load_chunk(
    uint32_t sbu, int stg, int tid,
    const __half* Ah, const __half* Al, const __half* Bh,
    long long aBase, long long bBase, int lda, int ldb, int k0)
{
    const int lrow = tid >> 1;
    const int seg  = (tid & 1) * 16;
    const uint32_t sd = sbu + stg * STG_STR + lrow * RSTRIDE + seg * 2;
    const long long ga = aBase + (long long)lrow * lda + k0 + seg;
    const long long gb = bBase + (long long)lrow * ldb + k0 + seg;
    cpa16(sd,           Ah + ga); cpa16(sd + 16,           Ah + ga + 8);
    if (NPASS == 2) {
        cpa16(sd + OFF_ALO, Al + ga); cpa16(sd + OFF_ALO + 16, Al + ga + 8);
    }
    cpa16(sd + OFF_BHI, Bh + gb); cpa16(sd + OFF_BHI + 16, Bh + gb + 8);
    asm volatile("cp.async.commit_group;");
}

// ---- split-fp16 mainloop: C += (A_hi [+ A_lo]) * B_hi^T,  NPASS in {1,2} ----
// 3-stage cp.async pipeline, ONE __syncthreads per chunk.
template<int NPASS>
__device__ __forceinline__ void gemm_mainloop(
    uint32_t sbu, int tid, int lane, int wm, int wn,
    const __half* Ah, const __half* Al, const __half* Bh,
    long long aBase, long long bBase, int lda, int ldb, int nchunks,
    float c[4][4][4])
{
    const int laneRowA = (lane & 7) + ((lane >> 3) & 1) * 8;
    const int laneColA = ((lane >> 4) & 1) * 16;
    const int laneRowB = lane & 7;
    const int laneColB = ((lane >> 3) & 1) * 16;

    const uint32_t aAddr = (wm*64 + laneRowA) * RSTRIDE + laneColA;
    const uint32_t bAddr = (wn*32 + laneRowB) * RSTRIDE + laneColB;

    load_chunk<NPASS>(sbu, 0, tid, Ah, Al, Bh, aBase, bBase, lda, ldb, 0);
    load_chunk<NPASS>(sbu, 1, tid, Ah, Al, Bh, aBase, bBase, lda, ldb, 32);

    int stg = 2;
    for (int ch = 0; ch < nchunks; ch++) {
        asm volatile("cp.async.wait_group 1;");
        __syncthreads();

        if (ch + 2 < nchunks)
            load_chunk<NPASS>(sbu, stg, tid, Ah, Al, Bh, aBase, bBase, lda, ldb, (ch + 2) << 5);
        else
            asm volatile("cp.async.commit_group;");
        stg = (stg == 2) ? 0 : stg + 1;

        const uint32_t sb = sbu + (ch % 3) * STG_STR;
        #pragma unroll
        for (int h = 0; h < 2; h++) {
            const uint32_t hoff = h * 32;
            uint32_t bh[4][2];
            #pragma unroll
            for (int nt = 0; nt < 4; nt++)
                ldsm2(bh[nt], sb + OFF_BHI + bAddr + nt*8*RSTRIDE + hoff);
            uint32_t a[4][4];
            // pass 1: A_hi x B_hi
            #pragma unroll
            for (int mt = 0; mt < 4; mt++)
                ldsm4(a[mt], sb + aAddr + mt*16*RSTRIDE + hoff);
            #pragma unroll
            for (int mt = 0; mt < 4; mt++)
                #pragma unroll
                for (int nt = 0; nt < 4; nt++)
                    mma16816(c[mt][nt], a[mt], bh[nt]);
            if (NPASS == 2) {
                // pass 2: A_lo x B_hi
                #pragma unroll
                for (int mt = 0; mt < 4; mt++)
                    ldsm4(a[mt], sb + OFF_ALO + aAddr + mt*16*RSTRIDE + hoff);
                #pragma unroll
                for (int mt = 0; mt < 4; mt++)
                    #pragma unroll
                    for (int nt = 0; nt < 4; nt++)
                        mma16816(c[mt][nt], a[mt], bh[nt]);
            }
        }
    }
}

// ---- epilogue: store fp16 hi only, row-major [row*DQ+col] (q, k) ----
__device__ __forceinline__ void epi_hi(float c[4][4][4], int lane, int wm, int wn,
    long long bm, int bn, __half* Oh)
{
    const int qrow = lane >> 2, qcol = (lane & 3) * 2;
    #pragma unroll
    for (int mt = 0; mt < 4; mt++)
        #pragma unroll
        for (int i = 0; i < 2; i++) {
            const long long row = bm + wm*64 + mt*16 + qrow + i*8;
            #pragma unroll
            for (int nt = 0; nt < 4; nt++) {
                const int col = bn + wn*32 + nt*8 + qcol;
                *(uint32_t*)(Oh + row*DQ + col) = pack2h(c[mt][nt][2*i], c[mt][nt][2*i+1]);
            }
        }
}

// ---- epilogue: store fp16 hi only, transposed [col*MR + row] (v^T) ----
__device__ __forceinline__ void epi_hiT(float c[4][4][4], int lane, int wm, int wn,
    long long bm, int bn, __half* Oh)
{
    const int qrow = lane >> 2, qcol = (lane & 3) * 2;
    #pragma unroll
    for (int mt = 0; mt < 4; mt++)
        #pragma unroll
        for (int i = 0; i < 2; i++) {
            const long long row = bm + wm*64 + mt*16 + qrow + i*8;
            #pragma unroll
            for (int nt = 0; nt < 4; nt++)
                #pragma unroll
                for (int j = 0; j < 2; j++) {
                    const long long colg = bn + wn*32 + nt*8 + qcol + j;
                    Oh[colg*MR + row] = __float2half_rn(c[mt][nt][2*i+j]);
                }
        }
}

// ============================================================================
// Fused projection kernel (2-pass): z=0 -> q hi, z=1 -> k hi, z=2 -> v hi^T
// ============================================================================
__global__ __launch_bounds__(256)
void proj_gemm()
{
    extern __shared__ char smem[];
    const uint32_t sbu = smem_u32(smem);
    const int tid = threadIdx.x, lane = tid & 31, wid = tid >> 5;
    const int wm = wid >> 2, wn = wid & 3;
    const int bm = blockIdx.y << 7, bn = blockIdx.x << 7;
    const int z = blockIdx.z;

    float c[4][4][4];
    #pragma unroll
    for (int i = 0; i < 4; i++)
        #pragma unroll
        for (int j = 0; j < 4; j++)
            { c[i][j][0]=0.f; c[i][j][1]=0.f; c[i][j][2]=0.f; c[i][j][3]=0.f; }

    gemm_mainloop<2>(sbu, tid, lane, wm, wn,
                     g_s.xhi[z], g_s.xlo[z], g_s.wthi[z],
                     (long long)bm * DQ, (long long)bn * DQ, DQ, DQ, DQ >> 5, c);

    if (z == 0)      epi_hi (c, lane, wm, wn, bm, bn, g_s.qhi);
    else if (z == 1) epi_hi (c, lane, wm, wn, bm, bn, g_s.khi);
    else             epi_hiT(c, lane, wm, wn, bm, bn, g_s.vthi);
}

// ============================================================================
// QK kernel (1-pass): raw logits (scale+mask, jax rounding) -> p, tile stats
// ============================================================================
__global__ __launch_bounds__(256)
void qk_gemm(float* __restrict__ outF, const float* __restrict__ mask)
{
    extern __shared__ char smem[];
    const uint32_t sbu = smem_u32(smem);
    const int tid = threadIdx.x, lane = tid & 31, wid = tid >> 5;
    const int wm = wid >> 2, wn = wid & 3;
    const int bm = blockIdx.y << 7, bn = blockIdx.x << 7;
    const long long zOff = (long long)blockIdx.z * SQ * DQ;

    float c[4][4][4];
    #pragma unroll
    for (int i = 0; i < 4; i++)
        #pragma unroll
        for (int j = 0; j < 4; j++)
            { c[i][j][0]=0.f; c[i][j][1]=0.f; c[i][j][2]=0.f; c[i][j][3]=0.f; }

    gemm_mainloop<1>(sbu, tid, lane, wm, wn,
                     g_s.qhi, nullptr, g_s.khi,
                     zOff + (long long)bm * DQ, zOff + (long long)bn * DQ,
                     DQ, DQ, DQ >> 5, c);

    const float scale = 0.044194173824159216f;  // 1/sqrt(512)
    const int qrow = lane >> 2, qcol = (lane & 3) * 2;
    float* smax = (float*)(smem + SM_STATS);    // [4][128]
    float* ssum = smax + 512;
    #pragma unroll
    for (int mt = 0; mt < 4; mt++)
        #pragma unroll
        for (int i = 0; i < 2; i++) {
            const int rowLocal = wm*64 + mt*16 + qrow + i*8;
            const long long grow = (long long)blockIdx.z * SQ + bm + rowLocal;
            float s[8];
            #pragma unroll
            for (int nt = 0; nt < 4; nt++) {
                const int col = bn + wn*32 + nt*8 + qcol;
                const float2 m = *(const float2*)(mask + grow*SQ + col);
                s[2*nt]   = __fadd_rn(__fmul_rn(c[mt][nt][2*i],   scale), __fmul_rn(m.x, -1e9f));
                s[2*nt+1] = __fadd_rn(__fmul_rn(c[mt][nt][2*i+1], scale), __fmul_rn(m.y, -1e9f));
                *(float2*)(outF + grow*SQ + col) = make_float2(s[2*nt], s[2*nt+1]);
            }
            float mx = s[0];
            #pragma unroll
            for (int j = 1; j < 8; j++) mx = fmaxf(mx, s[j]);
            mx = fmaxf(mx, __shfl_xor_sync(0xffffffffu, mx, 1));
            mx = fmaxf(mx, __shfl_xor_sync(0xffffffffu, mx, 2));
            float es = 0.f;
            #pragma unroll
            for (int j = 0; j < 8; j++) es += __expf(s[j] - mx);
            es += __shfl_xor_sync(0xffffffffu, es, 1);
            es += __shfl_xor_sync(0xffffffffu, es, 2);
            if ((lane & 3) == 0) {
                smax[wn*128 + rowLocal] = mx;
                ssum[wn*128 + rowLocal] = es;
            }
        }
    __syncthreads();
    if (tid < 128) {
        float m = smax[tid];
        #pragma unroll
        for (int w = 1; w < 4; w++) m = fmaxf(m, smax[w*128 + tid]);
        float l = 0.f;
        #pragma unroll
        for (int w = 0; w < 4; w++)
            l += ssum[w*128 + tid] * __expf(smax[w*128 + tid] - m);
        const long long grow = (long long)blockIdx.z * SQ + bm + tid;
        g_s.tmax[grow*16 + blockIdx.x] = m;
        g_s.tsum[grow*16 + blockIdx.x] = l;
    }
}

// ============================================================================
// PV kernel (1-pass): h = p_hi @ v_hi^T, fp32 out
// ============================================================================
__global__ __launch_bounds__(256)
void pv_gemm(float* __restrict__ outF)
{
    extern __shared__ char smem[];
    const uint32_t sbu = smem_u32(smem);
    const int tid = threadIdx.x, lane = tid & 31, wid = tid >> 5;
    const int wm = wid >> 2, wn = wid & 3;
    const int bm = blockIdx.y << 7, bn = blockIdx.x << 7;

    float c[4][4][4];
    #pragma unroll
    for (int i = 0; i < 4; i++)
        #pragma unroll
        for (int j = 0; j < 4; j++)
            { c[i][j][0]=0.f; c[i][j][1]=0.f; c[i][j][2]=0.f; c[i][j][3]=0.f; }

    gemm_mainloop<1>(sbu, tid, lane, wm, wn,
                     g_s.phi, nullptr, g_s.vthi,
                     ((long long)blockIdx.z * SQ + bm) * SQ,
                     (long long)bn * MR + (long long)blockIdx.z * SQ,
                     SQ, MR, SQ >> 5, c);

    const int qrow = lane >> 2, qcol = (lane & 3) * 2;
    #pragma unroll
    for (int mt = 0; mt < 4; mt++)
        #pragma unroll
        for (int i = 0; i < 2; i++) {
            const long long grow = (long long)blockIdx.z * SQ + bm + wm*64 + mt*16 + qrow + i*8;
            #pragma unroll
            for (int nt = 0; nt < 4; nt++) {
                const int col = bn + wn*32 + nt*8 + qcol;
                *(float2*)(outF + grow*DQ + col) =
                    make_float2(c[mt][nt][2*i], c[mt][nt][2*i+1]);
            }
        }
}

// ============================================================================
// Fused elementwise input split: z selects (qx, kx, vx) -> xhi[z], xlo[z]
// ============================================================================
__global__ __launch_bounds__(256)
void x_split(const float* __restrict__ X0, const float* __restrict__ X1,
             const float* __restrict__ X2)
{
    const int z = blockIdx.z;
    const float* X = (z == 0) ? X0 : (z == 1) ? X1 : X2;
    __half* H = g_s.xhi[z];
    __half* L = g_s.xlo[z];
    const size_t i = ((size_t)blockIdx.x * 256 + threadIdx.x) * 4;
    float4 v = *(const float4*)(X + i);
    uint32_t h0, l0, h1, l1;
    split2h(v.x, v.y, h0, l0);
    split2h(v.z, v.w, h1, l1);
    *(uint2*)(H + i) = make_uint2(h0, h1);
    *(uint2*)(L + i) = make_uint2(l0, l1);
}

// ============================================================================
// Fused weight transpose (smem-tiled), hi only: Wt[d][f] = fp16(W[f][d])
// ============================================================================
__global__ __launch_bounds__(256)
void wt_split(const float* __restrict__ W0, const float* __restrict__ W1,
              const float* __restrict__ W2)
{
    const int z = blockIdx.z;
    const float* W = (z == 0) ? W0 : (z == 1) ? W1 : W2;
    __half* Th = g_s.wthi[z];
    __shared__ float t[32][33];
    const int bf = blockIdx.y << 5, bd = blockIdx.x << 5;
    const int tx = threadIdx.x, ty = threadIdx.y;
    #pragma unroll
    for (int r = 0; r < 4; r++)
        t[ty + r*8][tx] = W[(bf + ty + r*8) * DQ + bd + tx];
    __syncthreads();
    #pragma unroll
    for (int r = 0; r < 4; r++) {
        const float v = t[tx][ty + r*8];
        const int dd = bd + ty + r*8, f = bf + tx;
        Th[dd * DQ + f] = __float2half_rn(v);
    }
}

// ============================================================================
// Softmax normalize: p = exp(s-m)/l (fp32 out) + fp16 hi copy for PV
// ============================================================================
__global__ __launch_bounds__(256)
void softmax_norm_kernel(float* __restrict__ p)
{
    const int g = blockIdx.x;
    __shared__ float sh[2];
    if (threadIdx.x == 0) {
        float m = __int_as_float(0xff800000);
        #pragma unroll
        for (int t = 0; t < 16; t++) m = fmaxf(m, g_s.tmax[g * 16 + t]);
        float l = 0.f;
        #pragma unroll
        for (int t = 0; t < 16; t++)
            l += g_s.tsum[g * 16 + t] * __expf(g_s.tmax[g * 16 + t] - m);
        sh[0] = m;
        sh[1] = 1.f / l;
    }
    __syncthreads();
    const float m = sh[0], inv = sh[1];
    float* row = p + (size_t)g * SQ;
    __half* ph = g_s.phi + (size_t)g * SQ;
    #pragma unroll
    for (int it = 0; it < 2; it++) {
        const int i = (threadIdx.x << 2) + (it << 10);
        float4 v = *(float4*)&row[i];
        v.x = __expf(v.x - m) * inv;
        v.y = __expf(v.y - m) * inv;
        v.z = __expf(v.z - m) * inv;
        v.w = __expf(v.w - m) * inv;
        *(float4*)&row[i] = v;
        *(uint2*)(ph + i) = make_uint2(pack2h(v.x, v.y), pack2h(v.z, v.w));
    }
}

// ============================================================================
// Host launcher (graph-capturable: kernel launches only)
// ============================================================================
extern "C" void kernel_launch(void* const* d_in, const int* in_sizes, int n_in,
                              void* d_out, int out_size)
{
    const float* qx   = (const float*)d_in[0];
    const float* kx   = (const float*)d_in[1];
    const float* vx   = (const float*)d_in[2];
    const float* mask = (const float*)d_in[3];
    const float* Wq   = (const float*)d_in[4];
    const float* Wk   = (const float*)d_in[5];
    const float* Wv   = (const float*)d_in[6];

    float* h = (float*)d_out;                  // [8,2048,512]
    float* p = h + (size_t)MR * DQ;            // [8,2048,2048]

    static bool attr_done = false;
    if (!attr_done) {
        cudaFuncSetAttribute(proj_gemm, cudaFuncAttributeMaxDynamicSharedMemorySize, SM_TOTAL);
        cudaFuncSetAttribute(qk_gemm,   cudaFuncAttributeMaxDynamicSharedMemorySize, SM_TOTAL);
        cudaFuncSetAttribute(pv_gemm,   cudaFuncAttributeMaxDynamicSharedMemorySize, SM_TOTAL);
        attr_done = true;
    }

    // 1) split inputs + transpose weights (fused over z=3)
    x_split<<<dim3((MR * DQ) / 1024, 1, 3), 256>>>(qx, kx, vx);
    wt_split<<<dim3(16, 16, 3), dim3(32, 8)>>>(Wq, Wk, Wv);

    // 2) fused projections (2-pass; z: 0=q hi, 1=k hi, 2=v hi^T)
    proj_gemm<<<dim3(4, 128, 3), 256, SM_TOTAL>>>();

    // 3) QK^T (1-pass) + scale + mask -> raw logits in p + per-tile stats
    qk_gemm<<<dim3(16, 16, NB), 256, SM_TOTAL>>>(p, mask);

    // 4) normalize p in place + emit fp16 p for PV
    softmax_norm_kernel<<<dim3(MR), 256>>>(p);

    // 5) h = p @ v (1-pass)
    pv_gemm<<<dim3(4, 16, NB), 256, SM_TOTAL>>>(h);
}